// round 2
// baseline (speedup 1.0000x reference)
#include <cuda_runtime.h>
#include <math.h>

#define BB 4
#define CH 64
#define NP 8192
#define KK 16
#define TOT (BB*NP)   /* 32768 points */

// ---------------- scratch (device globals; no allocation allowed) ----------------
__device__ float g_ft[TOT*CH];       // features, point-major  [p][c]
__device__ float g_phit[TOT*CH];     // phi,  point-major
__device__ float g_psit[TOT*CH];     // psi,  point-major
__device__ float g_alphat[TOT*CH];   // alpha, point-major
__device__ float g_sqn[TOT];         // |f|^2 per point
__device__ float g_coordst[TOT*3];   // coords, point-major [p][3]
__device__ int   g_knn[TOT*KK];      // knn indices
__device__ float g_WTd2[CH*CH];      // W_d2 transposed [c][o]
__device__ float g_WTg1[CH*CH];      // W_g1 transposed [c][o]
__device__ float g_WTg2[CH*CH];      // W_g2 transposed [c][o]

// ======================= Kernel 1: projections + transposes =======================
// grid 512 x 256 threads. Each block: 8 warps x 8 points = 64 points.
__global__ void __launch_bounds__(256) proj_kernel(
    const float* __restrict__ feat, const float* __restrict__ coords,
    const float* __restrict__ Wphi, const float* __restrict__ bphi,
    const float* __restrict__ Wpsi, const float* __restrict__ bpsi,
    const float* __restrict__ Wal,  const float* __restrict__ bal,
    const float* __restrict__ Wg1,  const float* __restrict__ Wg2,
    const float* __restrict__ Wd2)
{
    __shared__ float WT[CH*CH];        // 16KB, one matrix at a time, [c][o]
    __shared__ float fbuf[8][8][CH];   // 16KB, [warp][pt][c]

    const int tid = threadIdx.x;
    const int w = tid >> 5, l = tid & 31;

    // coords transpose (grid-stride over all points)
    for (int p = blockIdx.x * 256 + tid; p < TOT; p += gridDim.x * 256) {
        int b = p >> 13, nn = p & (NP - 1);
        const float* cs = coords + b * 3 * NP + nn;
        g_coordst[p*3 + 0] = cs[0];
        g_coordst[p*3 + 1] = cs[NP];
        g_coordst[p*3 + 2] = cs[2*NP];
    }
    // weight transposes into global scratch (block 0 only)
    if (blockIdx.x == 0) {
        for (int i = tid; i < CH*CH; i += 256) {
            int o = i >> 6, c = i & 63;
            g_WTd2[c*CH + o] = Wd2[i];
            g_WTg1[c*CH + o] = Wg1[i];
            g_WTg2[c*CH + o] = Wg2[i];
        }
    }

    const int pbase = blockIdx.x * 64;

    // stage this warp's 8 points' features; also write f_t and sqnorm
    #pragma unroll
    for (int i = 0; i < 8; i++) {
        int p = pbase + w * 8 + i;
        int b = p >> 13, nn = p & (NP - 1);
        float f0 = feat[(b*CH + 2*l    ) * NP + nn];
        float f1 = feat[(b*CH + 2*l + 1) * NP + nn];
        fbuf[w][i][2*l]     = f0;
        fbuf[w][i][2*l + 1] = f1;
        *(float2*)&g_ft[p*CH + 2*l] = make_float2(f0, f1);
        float sq = f0*f0 + f1*f1;
        #pragma unroll
        for (int off = 16; off; off >>= 1) sq += __shfl_xor_sync(0xffffffffu, sq, off);
        if (l == 0) g_sqn[p] = sq;
    }

    // three 64x64 matvecs per point: phi, psi, alpha
    #pragma unroll 1
    for (int mat = 0; mat < 3; mat++) {
        const float* Wg = (mat == 0) ? Wphi : (mat == 1) ? Wpsi : Wal;
        const float* bg = (mat == 0) ? bphi : (mat == 1) ? bpsi : bal;
        float*       og = (mat == 0) ? g_phit : (mat == 1) ? g_psit : g_alphat;
        __syncthreads();
        for (int i = tid; i < CH*CH; i += 256) WT[(i & 63)*CH + (i >> 6)] = Wg[i];
        __syncthreads();
        float bb0 = bg[2*l], bb1 = bg[2*l + 1];
        #pragma unroll 1
        for (int i = 0; i < 8; i++) {
            int p = pbase + w * 8 + i;
            float a0 = bb0, a1 = bb1;
            const float4* fv4 = (const float4*)fbuf[w][i];
            #pragma unroll
            for (int c4 = 0; c4 < 16; c4++) {
                float4 fv = fv4[c4];
                float2 w0 = *(const float2*)&WT[(4*c4 + 0)*CH + 2*l];
                float2 w1 = *(const float2*)&WT[(4*c4 + 1)*CH + 2*l];
                float2 w2 = *(const float2*)&WT[(4*c4 + 2)*CH + 2*l];
                float2 w3 = *(const float2*)&WT[(4*c4 + 3)*CH + 2*l];
                a0 = fmaf(w0.x, fv.x, a0); a1 = fmaf(w0.y, fv.x, a1);
                a0 = fmaf(w1.x, fv.y, a0); a1 = fmaf(w1.y, fv.y, a1);
                a0 = fmaf(w2.x, fv.z, a0); a1 = fmaf(w2.y, fv.z, a1);
                a0 = fmaf(w3.x, fv.w, a0); a1 = fmaf(w3.y, fv.w, a1);
            }
            *(float2*)&og[p*CH + 2*l] = make_float2(a0, a1);
        }
    }
}

// ======================= Kernel 2: fused distance + top-16 =======================
// grid 256 x 128 threads. One thread owns one query; block streams all candidates.
// Ranking metric: 2*dot(q,m) - |m|^2  (== reference neg_d + const |q|^2).
__global__ void __launch_bounds__(128) knn_kernel() {
    __shared__ float sh[128 * 68];   // candidate tile [128][64], rows padded to 68 floats
    __shared__ float sqsh[128];

    const int tid = threadIdx.x;
    const int b = blockIdx.x >> 6;                 // 64 blocks per batch
    const int q = ((blockIdx.x & 63) << 7) | tid;  // query index within batch
    const float* ft = g_ft + b * NP * CH;

    float qv[64];
    {
        const float4* qp = (const float4*)(ft + q * CH);
        #pragma unroll
        for (int j = 0; j < 16; j++) {
            float4 v = qp[j];
            qv[4*j] = v.x; qv[4*j+1] = v.y; qv[4*j+2] = v.z; qv[4*j+3] = v.w;
        }
    }

    float bd[16]; int bi[16];
    #pragma unroll
    for (int t = 0; t < 16; t++) { bd[t] = -3.0e38f; bi[t] = 0; }
    float thr = -3.0e38f;
    int   minpos = 0;

    for (int tb = 0; tb < NP; tb += 128) {
        __syncthreads();
        // stage 128 candidates (coalesced float4 reads)
        const float4* src = (const float4*)(ft + tb * CH);
        #pragma unroll
        for (int it = 0; it < 16; it++) {
            int i4 = tid + it * 128;          // 0..2047
            int mi = i4 >> 4, c4 = i4 & 15;
            *(float4*)&sh[mi * 68 + 4 * c4] = src[i4];
        }
        sqsh[tid] = g_sqn[b * NP + tb + tid];
        __syncthreads();

        #pragma unroll 1
        for (int mi = 0; mi < 128; mi++) {
            const float4* row = (const float4*)&sh[mi * 68];  // uniform -> broadcast LDS
            float a0 = 0.f, a1 = 0.f, a2 = 0.f, a3 = 0.f;
            #pragma unroll
            for (int j = 0; j < 16; j++) {
                float4 v = row[j];
                a0 = fmaf(qv[4*j    ], v.x, a0);
                a1 = fmaf(qv[4*j + 1], v.y, a1);
                a2 = fmaf(qv[4*j + 2], v.z, a2);
                a3 = fmaf(qv[4*j + 3], v.w, a3);
            }
            float val = fmaf(2.f, (a0 + a1) + (a2 + a3), -sqsh[mi]);
            if (val > thr) {
                int m = tb + mi;
                #pragma unroll
                for (int t = 0; t < 16; t++) if (t == minpos) { bd[t] = val; bi[t] = m; }
                thr = bd[0]; minpos = 0;
                #pragma unroll
                for (int t = 1; t < 16; t++) if (bd[t] < thr) { thr = bd[t]; minpos = t; }
            }
        }
    }

    int* dst = g_knn + (b * NP + q) * KK;
    #pragma unroll
    for (int t = 0; t < 16; t++) dst[t] = bi[t];
}

// ======================= Kernel 3: per-neighbor MLP + softmax ====================
// grid 1024 x 128 threads (4 warps). Warp per point; lane owns output rows 2l,2l+1.
__global__ void __launch_bounds__(128) agg_kernel(
    const float* __restrict__ Wd1, const float* __restrict__ bd1,
    const float* __restrict__ bd2, const float* __restrict__ bg1,
    const float* __restrict__ bg2, float* __restrict__ out)
{
    __shared__ float bufA[4][CH * 20];   // h, then x   (rows padded to 20 floats)
    __shared__ float bufB[4][CH * 20];   // g
    __shared__ float cds[4][48];         // coord diffs [3][16]
    __shared__ int   idxs[4][16];

    const int w = threadIdx.x >> 5, l = threadIdx.x & 31;
    const int r0 = 2 * l, r1 = 2 * l + 1;

    const float w00 = Wd1[r0*3+0], w01 = Wd1[r0*3+1], w02 = Wd1[r0*3+2];
    const float w10 = Wd1[r1*3+0], w11 = Wd1[r1*3+1], w12 = Wd1[r1*3+2];
    const float bd1_0 = bd1[r0], bd1_1 = bd1[r1];
    const float bd2_0 = bd2[r0], bd2_1 = bd2[r1];
    const float bg1_0 = bg1[r0], bg1_1 = bg1[r1];
    const float bg2_0 = bg2[r0], bg2_1 = bg2[r1];

    #pragma unroll 1
    for (int i = 0; i < 8; i++) {
        const int p = (blockIdx.x * 4 + w) * 8 + i;
        const int b = p >> 13, n = p & (NP - 1);

        // S0: neighbor indices + coord diffs
        if (l < 16) {
            int m = g_knn[p * KK + l];
            idxs[w][l] = m;
            const float* cn = g_coordst + p * 3;
            const float* cm = g_coordst + (b * NP + m) * 3;
            cds[w][l]      = cn[0] - cm[0];
            cds[w][16 + l] = cn[1] - cm[1];
            cds[w][32 + l] = cn[2] - cm[2];
        }
        __syncwarp();

        // S1: h = relu(Wd1 * cdiff + bd1)  -> bufA
        #pragma unroll
        for (int k = 0; k < 16; k++) {
            float c0 = cds[w][k], c1 = cds[w][16 + k], c2 = cds[w][32 + k];
            float h0 = fmaxf(fmaf(w02, c2, fmaf(w01, c1, fmaf(w00, c0, bd1_0))), 0.f);
            float h1 = fmaxf(fmaf(w12, c2, fmaf(w11, c1, fmaf(w10, c0, bd1_1))), 0.f);
            bufA[w][r0*20 + k] = h0;
            bufA[w][r1*20 + k] = h1;
        }
        __syncwarp();

        // S2: delta = Wd2 * h + bd2   (kept in registers d0/d1)
        float d0[16], d1[16];
        #pragma unroll
        for (int k = 0; k < 16; k++) { d0[k] = bd2_0; d1[k] = bd2_1; }
        #pragma unroll 4
        for (int c = 0; c < CH; c++) {
            float2 wv = *(const float2*)&g_WTd2[c*CH + r0];
            const float4* hr = (const float4*)&bufA[w][c*20];
            #pragma unroll
            for (int j = 0; j < 4; j++) {
                float4 h4 = hr[j];
                d0[4*j  ] = fmaf(wv.x, h4.x, d0[4*j  ]); d1[4*j  ] = fmaf(wv.y, h4.x, d1[4*j  ]);
                d0[4*j+1] = fmaf(wv.x, h4.y, d0[4*j+1]); d1[4*j+1] = fmaf(wv.y, h4.y, d1[4*j+1]);
                d0[4*j+2] = fmaf(wv.x, h4.z, d0[4*j+2]); d1[4*j+2] = fmaf(wv.y, h4.z, d1[4*j+2]);
                d0[4*j+3] = fmaf(wv.x, h4.w, d0[4*j+3]); d1[4*j+3] = fmaf(wv.y, h4.w, d1[4*j+3]);
            }
        }
        __syncwarp();   // all lanes finished reading h before x overwrites bufA

        // S3: x = phi - psi[idx] + delta  -> bufA (overwrite h)
        {
            float2 ph = *(const float2*)&g_phit[p*CH + r0];
            #pragma unroll
            for (int k = 0; k < 16; k++) {
                int m = idxs[w][k];
                float2 ps = *(const float2*)&g_psit[(size_t)(b*NP + m)*CH + r0];
                bufA[w][r0*20 + k] = ph.x - ps.x + d0[k];
                bufA[w][r1*20 + k] = ph.y - ps.y + d1[k];
            }
        }
        __syncwarp();

        // S4: g = relu(Wg1 * x + bg1) -> bufB
        {
            float g0[16], g1[16];
            #pragma unroll
            for (int k = 0; k < 16; k++) { g0[k] = bg1_0; g1[k] = bg1_1; }
            #pragma unroll 4
            for (int c = 0; c < CH; c++) {
                float2 wv = *(const float2*)&g_WTg1[c*CH + r0];
                const float4* xr = (const float4*)&bufA[w][c*20];
                #pragma unroll
                for (int j = 0; j < 4; j++) {
                    float4 x4 = xr[j];
                    g0[4*j  ] = fmaf(wv.x, x4.x, g0[4*j  ]); g1[4*j  ] = fmaf(wv.y, x4.x, g1[4*j  ]);
                    g0[4*j+1] = fmaf(wv.x, x4.y, g0[4*j+1]); g1[4*j+1] = fmaf(wv.y, x4.y, g1[4*j+1]);
                    g0[4*j+2] = fmaf(wv.x, x4.z, g0[4*j+2]); g1[4*j+2] = fmaf(wv.y, x4.z, g1[4*j+2]);
                    g0[4*j+3] = fmaf(wv.x, x4.w, g0[4*j+3]); g1[4*j+3] = fmaf(wv.y, x4.w, g1[4*j+3]);
                }
            }
            #pragma unroll
            for (int k = 0; k < 16; k++) {
                bufB[w][r0*20 + k] = fmaxf(g0[k], 0.f);
                bufB[w][r1*20 + k] = fmaxf(g1[k], 0.f);
            }
        }
        __syncwarp();

        // S5: gamma = Wg2 * g + bg2  (registers gm0/gm1)
        float gm0[16], gm1[16];
        #pragma unroll
        for (int k = 0; k < 16; k++) { gm0[k] = bg2_0; gm1[k] = bg2_1; }
        #pragma unroll 4
        for (int c = 0; c < CH; c++) {
            float2 wv = *(const float2*)&g_WTg2[c*CH + r0];
            const float4* gr = (const float4*)&bufB[w][c*20];
            #pragma unroll
            for (int j = 0; j < 4; j++) {
                float4 g4 = gr[j];
                gm0[4*j  ] = fmaf(wv.x, g4.x, gm0[4*j  ]); gm1[4*j  ] = fmaf(wv.y, g4.x, gm1[4*j  ]);
                gm0[4*j+1] = fmaf(wv.x, g4.y, gm0[4*j+1]); gm1[4*j+1] = fmaf(wv.y, g4.y, gm1[4*j+1]);
                gm0[4*j+2] = fmaf(wv.x, g4.z, gm0[4*j+2]); gm1[4*j+2] = fmaf(wv.y, g4.z, gm1[4*j+2]);
                gm0[4*j+3] = fmaf(wv.x, g4.w, gm0[4*j+3]); gm1[4*j+3] = fmaf(wv.y, g4.w, gm1[4*j+3]);
            }
        }

        // S6: softmax over k, combine with alpha + delta, write output
        {
            float mx0 = gm0[0], mx1 = gm1[0];
            #pragma unroll
            for (int k = 1; k < 16; k++) { mx0 = fmaxf(mx0, gm0[k]); mx1 = fmaxf(mx1, gm1[k]); }
            float s0 = 0.f, s1 = 0.f;
            #pragma unroll
            for (int k = 0; k < 16; k++) {
                gm0[k] = __expf(gm0[k] - mx0); s0 += gm0[k];
                gm1[k] = __expf(gm1[k] - mx1); s1 += gm1[k];
            }
            float2 al = *(const float2*)&g_alphat[p*CH + r0];
            float acc0 = 0.f, acc1 = 0.f;
            #pragma unroll
            for (int k = 0; k < 16; k++) {
                acc0 = fmaf(gm0[k], al.x + d0[k], acc0);
                acc1 = fmaf(gm1[k], al.y + d1[k], acc1);
            }
            out[(size_t)b*CH*NP + (size_t)r0*NP + n] = acc0 / s0;
            out[(size_t)b*CH*NP + (size_t)r1*NP + n] = acc1 / s1;
        }
        __syncwarp();
    }
}

extern "C" void kernel_launch(void* const* d_in, const int* in_sizes, int n_in,
                              void* d_out, int out_size) {
    const float* features = (const float*)d_in[0];
    const float* coords   = (const float*)d_in[1];
    const float* W_phi    = (const float*)d_in[2];
    const float* b_phi    = (const float*)d_in[3];
    const float* W_psi    = (const float*)d_in[4];
    const float* b_psi    = (const float*)d_in[5];
    const float* W_alpha  = (const float*)d_in[6];
    const float* b_alpha  = (const float*)d_in[7];
    const float* W_g1     = (const float*)d_in[8];
    const float* b_g1     = (const float*)d_in[9];
    const float* W_g2     = (const float*)d_in[10];
    const float* b_g2     = (const float*)d_in[11];
    const float* W_d1     = (const float*)d_in[12];
    const float* b_d1     = (const float*)d_in[13];
    const float* W_d2     = (const float*)d_in[14];
    const float* b_d2     = (const float*)d_in[15];
    float* out = (float*)d_out;

    proj_kernel<<<512, 256>>>(features, coords, W_phi, b_phi, W_psi, b_psi,
                              W_alpha, b_alpha, W_g1, W_g2, W_d2);
    knn_kernel<<<256, 128>>>();
    agg_kernel<<<1024, 128>>>(W_d1, b_d1, b_d2, b_g1, b_g2, out);
}

// round 3
// speedup vs baseline: 1.0812x; 1.0812x over previous
#include <cuda_runtime.h>
#include <math.h>

#define BB 4
#define CH 64
#define NP 8192
#define KK 16
#define TOT (BB*NP)   /* 32768 points */

typedef unsigned long long ull;

// ---------------- packed f32x2 helpers (Blackwell sm_100+) ----------------
#define FMA2(acc, a, b) asm("fma.rn.f32x2 %0, %1, %2, %0;" : "+l"(acc) : "l"(a), "l"(b))
#define MUL2(d, a, b)   asm("mul.rn.f32x2 %0, %1, %2;"    : "=l"(d)   : "l"(a), "l"(b))
#define ADD2(d, a, b)   asm("add.rn.f32x2 %0, %1, %2;"    : "=l"(d)   : "l"(a), "l"(b))

__device__ __forceinline__ ull pack2(float x, float y) {
    ull r;
    asm("mov.b64 %0, {%1, %2};" : "=l"(r) : "f"(x), "f"(y));
    return r;
}
__device__ __forceinline__ float2 unpack2(ull v) {
    float2 r;
    asm("mov.b64 {%0, %1}, %2;" : "=f"(r.x), "=f"(r.y) : "l"(v));
    return r;
}

// ---------------- scratch (device globals; no allocation allowed) ----------------
__device__ float g_ft[TOT*CH];       // features, point-major  [p][c]
__device__ float g_phit[TOT*CH];     // phi,  point-major
__device__ float g_psit[TOT*CH];     // psi,  point-major
__device__ float g_alphat[TOT*CH];   // alpha, point-major
__device__ float g_sqn[TOT];         // |f|^2 per point
__device__ float g_coordst[TOT*3];   // coords, point-major [p][3]
__device__ int   g_knn[TOT*KK];      // knn indices
__device__ float g_WTd2[CH*CH];      // W_d2 transposed [c][o]
__device__ float g_WTg1[CH*CH];      // W_g1 transposed [c][o]
__device__ float g_WTg2[CH*CH];      // W_g2 transposed [c][o]

// ======================= Kernel 1: projections + transposes =======================
__global__ void __launch_bounds__(256) proj_kernel(
    const float* __restrict__ feat, const float* __restrict__ coords,
    const float* __restrict__ Wphi, const float* __restrict__ bphi,
    const float* __restrict__ Wpsi, const float* __restrict__ bpsi,
    const float* __restrict__ Wal,  const float* __restrict__ bal,
    const float* __restrict__ Wg1,  const float* __restrict__ Wg2,
    const float* __restrict__ Wd2)
{
    __shared__ float WT[CH*CH];
    __shared__ float fbuf[8][8][CH];

    const int tid = threadIdx.x;
    const int w = tid >> 5, l = tid & 31;

    for (int p = blockIdx.x * 256 + tid; p < TOT; p += gridDim.x * 256) {
        int b = p >> 13, nn = p & (NP - 1);
        const float* cs = coords + b * 3 * NP + nn;
        g_coordst[p*3 + 0] = cs[0];
        g_coordst[p*3 + 1] = cs[NP];
        g_coordst[p*3 + 2] = cs[2*NP];
    }
    if (blockIdx.x == 0) {
        for (int i = tid; i < CH*CH; i += 256) {
            int o = i >> 6, c = i & 63;
            g_WTd2[c*CH + o] = Wd2[i];
            g_WTg1[c*CH + o] = Wg1[i];
            g_WTg2[c*CH + o] = Wg2[i];
        }
    }

    const int pbase = blockIdx.x * 64;

    #pragma unroll
    for (int i = 0; i < 8; i++) {
        int p = pbase + w * 8 + i;
        int b = p >> 13, nn = p & (NP - 1);
        float f0 = feat[(b*CH + 2*l    ) * NP + nn];
        float f1 = feat[(b*CH + 2*l + 1) * NP + nn];
        fbuf[w][i][2*l]     = f0;
        fbuf[w][i][2*l + 1] = f1;
        *(float2*)&g_ft[p*CH + 2*l] = make_float2(f0, f1);
        float sq = f0*f0 + f1*f1;
        #pragma unroll
        for (int off = 16; off; off >>= 1) sq += __shfl_xor_sync(0xffffffffu, sq, off);
        if (l == 0) g_sqn[p] = sq;
    }

    #pragma unroll 1
    for (int mat = 0; mat < 3; mat++) {
        const float* Wg = (mat == 0) ? Wphi : (mat == 1) ? Wpsi : Wal;
        const float* bg = (mat == 0) ? bphi : (mat == 1) ? bpsi : bal;
        float*       og = (mat == 0) ? g_phit : (mat == 1) ? g_psit : g_alphat;
        __syncthreads();
        for (int i = tid; i < CH*CH; i += 256) WT[(i & 63)*CH + (i >> 6)] = Wg[i];
        __syncthreads();
        float bb0 = bg[2*l], bb1 = bg[2*l + 1];
        #pragma unroll 1
        for (int i = 0; i < 8; i++) {
            int p = pbase + w * 8 + i;
            float a0 = bb0, a1 = bb1;
            const float4* fv4 = (const float4*)fbuf[w][i];
            #pragma unroll
            for (int c4 = 0; c4 < 16; c4++) {
                float4 fv = fv4[c4];
                float2 w0 = *(const float2*)&WT[(4*c4 + 0)*CH + 2*l];
                float2 w1 = *(const float2*)&WT[(4*c4 + 1)*CH + 2*l];
                float2 w2 = *(const float2*)&WT[(4*c4 + 2)*CH + 2*l];
                float2 w3 = *(const float2*)&WT[(4*c4 + 3)*CH + 2*l];
                a0 = fmaf(w0.x, fv.x, a0); a1 = fmaf(w0.y, fv.x, a1);
                a0 = fmaf(w1.x, fv.y, a0); a1 = fmaf(w1.y, fv.y, a1);
                a0 = fmaf(w2.x, fv.z, a0); a1 = fmaf(w2.y, fv.z, a1);
                a0 = fmaf(w3.x, fv.w, a0); a1 = fmaf(w3.y, fv.w, a1);
            }
            *(float2*)&og[p*CH + 2*l] = make_float2(a0, a1);
        }
    }
}

// ======================= Kernel 2: fused distance + top-16 (f32x2) ================
// grid 256 x 128 threads. One thread owns one query; block streams all candidates.
// Ranking metric: 2*dot(q,m) - |m|^2  (== reference neg_d + const |q|^2).
__global__ void __launch_bounds__(128) knn_kernel() {
    __shared__ float sh[128 * 68];   // candidate tile [128][64], rows padded to 68 floats
    __shared__ float sqsh[128];

    const int tid = threadIdx.x;
    const int b = blockIdx.x >> 6;
    const int q = ((blockIdx.x & 63) << 7) | tid;
    const float* ft = g_ft + b * NP * CH;

    // query vector packed as 32 x f32x2
    ull qp[32];
    {
        const float4* qpv = (const float4*)(ft + q * CH);
        #pragma unroll
        for (int j = 0; j < 16; j++) {
            float4 v = qpv[j];
            qp[2*j]     = pack2(v.x, v.y);
            qp[2*j + 1] = pack2(v.z, v.w);
        }
    }

    float bd[16]; int bi[16];
    #pragma unroll
    for (int t = 0; t < 16; t++) { bd[t] = -3.0e38f; bi[t] = 0; }
    float thr = -3.0e38f;
    int   minpos = 0;

    for (int tb = 0; tb < NP; tb += 128) {
        __syncthreads();
        const float4* src = (const float4*)(ft + tb * CH);
        #pragma unroll
        for (int it = 0; it < 16; it++) {
            int i4 = tid + it * 128;
            int mi = i4 >> 4, c4 = i4 & 15;
            *(float4*)&sh[mi * 68 + 4 * c4] = src[i4];
        }
        sqsh[tid] = g_sqn[b * NP + tb + tid];
        __syncthreads();

        #pragma unroll 1
        for (int mi = 0; mi < 128; mi++) {
            const float4* row = (const float4*)&sh[mi * 68];  // uniform -> broadcast LDS
            ull a0, a1, a2, a3;
            {   // j = 0, 1 : start with mul (no zero-init)
                float4 v0 = row[0];
                MUL2(a0, qp[0], pack2(v0.x, v0.y));
                MUL2(a1, qp[1], pack2(v0.z, v0.w));
                float4 v1 = row[1];
                MUL2(a2, qp[2], pack2(v1.x, v1.y));
                MUL2(a3, qp[3], pack2(v1.z, v1.w));
            }
            #pragma unroll
            for (int j = 2; j < 16; j += 2) {
                float4 v0 = row[j];
                FMA2(a0, qp[2*j],     pack2(v0.x, v0.y));
                FMA2(a1, qp[2*j + 1], pack2(v0.z, v0.w));
                float4 v1 = row[j + 1];
                FMA2(a2, qp[2*j + 2], pack2(v1.x, v1.y));
                FMA2(a3, qp[2*j + 3], pack2(v1.z, v1.w));
            }
            ADD2(a0, a0, a2);
            ADD2(a1, a1, a3);
            ADD2(a0, a0, a1);
            float2 s = unpack2(a0);
            float val = fmaf(2.f, s.x + s.y, -sqsh[mi]);
            if (val > thr) {
                int m = tb + mi;
                #pragma unroll
                for (int t = 0; t < 16; t++) if (t == minpos) { bd[t] = val; bi[t] = m; }
                thr = bd[0]; minpos = 0;
                #pragma unroll
                for (int t = 1; t < 16; t++) if (bd[t] < thr) { thr = bd[t]; minpos = t; }
            }
        }
    }

    int* dst = g_knn + (b * NP + q) * KK;
    #pragma unroll
    for (int t = 0; t < 16; t++) dst[t] = bi[t];
}

// ======================= Kernel 3: per-neighbor MLP + softmax (f32x2 GEMMs) =======
// grid 1024 x 128 threads (4 warps). Warp per point; lane owns output rows 2l,2l+1.
__global__ void __launch_bounds__(128) agg_kernel(
    const float* __restrict__ Wd1, const float* __restrict__ bd1,
    const float* __restrict__ bd2, const float* __restrict__ bg1,
    const float* __restrict__ bg2, float* __restrict__ out)
{
    __shared__ float bufA[4][CH * 20];   // h, then x   (rows padded to 20 floats)
    __shared__ float bufB[4][CH * 20];   // g
    __shared__ float cds[4][48];         // coord diffs [3][16]
    __shared__ int   idxs[4][16];

    const int w = threadIdx.x >> 5, l = threadIdx.x & 31;
    const int r0 = 2 * l, r1 = 2 * l + 1;

    const float w00 = Wd1[r0*3+0], w01 = Wd1[r0*3+1], w02 = Wd1[r0*3+2];
    const float w10 = Wd1[r1*3+0], w11 = Wd1[r1*3+1], w12 = Wd1[r1*3+2];
    const float bd1_0 = bd1[r0], bd1_1 = bd1[r1];
    const float bd2_0 = bd2[r0], bd2_1 = bd2[r1];
    const float bg1_0 = bg1[r0], bg1_1 = bg1[r1];
    const float bg2_0 = bg2[r0], bg2_1 = bg2[r1];

    #pragma unroll 1
    for (int i = 0; i < 8; i++) {
        const int p = (blockIdx.x * 4 + w) * 8 + i;
        const int b = p >> 13, n = p & (NP - 1);

        // S0: neighbor indices + coord diffs
        if (l < 16) {
            int m = g_knn[p * KK + l];
            idxs[w][l] = m;
            const float* cn = g_coordst + p * 3;
            const float* cm = g_coordst + (b * NP + m) * 3;
            cds[w][l]      = cn[0] - cm[0];
            cds[w][16 + l] = cn[1] - cm[1];
            cds[w][32 + l] = cn[2] - cm[2];
        }
        __syncwarp();

        // S1: h = relu(Wd1 * cdiff + bd1)  -> bufA
        #pragma unroll
        for (int k = 0; k < 16; k++) {
            float c0 = cds[w][k], c1 = cds[w][16 + k], c2 = cds[w][32 + k];
            float h0 = fmaxf(fmaf(w02, c2, fmaf(w01, c1, fmaf(w00, c0, bd1_0))), 0.f);
            float h1 = fmaxf(fmaf(w12, c2, fmaf(w11, c1, fmaf(w10, c0, bd1_1))), 0.f);
            bufA[w][r0*20 + k] = h0;
            bufA[w][r1*20 + k] = h1;
        }
        __syncwarp();

        // S2: delta = Wd2 * h + bd2   (packed accumulators over k-pairs)
        ull D0[8], D1[8];
        {
            ull b0 = pack2(bd2_0, bd2_0), b1 = pack2(bd2_1, bd2_1);
            #pragma unroll
            for (int j = 0; j < 8; j++) { D0[j] = b0; D1[j] = b1; }
        }
        #pragma unroll 4
        for (int c = 0; c < CH; c++) {
            float2 wv = *(const float2*)&g_WTd2[c*CH + r0];
            ull wx = pack2(wv.x, wv.x), wy = pack2(wv.y, wv.y);
            const float4* hr = (const float4*)&bufA[w][c*20];
            #pragma unroll
            for (int j = 0; j < 4; j++) {
                float4 h4 = hr[j];
                ull lo = pack2(h4.x, h4.y), hi = pack2(h4.z, h4.w);
                FMA2(D0[2*j], wx, lo); FMA2(D0[2*j+1], wx, hi);
                FMA2(D1[2*j], wy, lo); FMA2(D1[2*j+1], wy, hi);
            }
        }
        float d0[16], d1[16];
        #pragma unroll
        for (int j = 0; j < 8; j++) {
            float2 u = unpack2(D0[j]); d0[2*j] = u.x; d0[2*j+1] = u.y;
            float2 v = unpack2(D1[j]); d1[2*j] = v.x; d1[2*j+1] = v.y;
        }
        __syncwarp();   // all lanes finished reading h before x overwrites bufA

        // S3: x = phi - psi[idx] + delta  -> bufA (overwrite h)
        {
            float2 ph = *(const float2*)&g_phit[p*CH + r0];
            #pragma unroll
            for (int k = 0; k < 16; k++) {
                int m = idxs[w][k];
                float2 ps = *(const float2*)&g_psit[(size_t)(b*NP + m)*CH + r0];
                bufA[w][r0*20 + k] = ph.x - ps.x + d0[k];
                bufA[w][r1*20 + k] = ph.y - ps.y + d1[k];
            }
        }
        __syncwarp();

        // S4: g = relu(Wg1 * x + bg1) -> bufB
        {
            ull G0[8], G1[8];
            {
                ull b0 = pack2(bg1_0, bg1_0), b1 = pack2(bg1_1, bg1_1);
                #pragma unroll
                for (int j = 0; j < 8; j++) { G0[j] = b0; G1[j] = b1; }
            }
            #pragma unroll 4
            for (int c = 0; c < CH; c++) {
                float2 wv = *(const float2*)&g_WTg1[c*CH + r0];
                ull wx = pack2(wv.x, wv.x), wy = pack2(wv.y, wv.y);
                const float4* xr = (const float4*)&bufA[w][c*20];
                #pragma unroll
                for (int j = 0; j < 4; j++) {
                    float4 x4 = xr[j];
                    ull lo = pack2(x4.x, x4.y), hi = pack2(x4.z, x4.w);
                    FMA2(G0[2*j], wx, lo); FMA2(G0[2*j+1], wx, hi);
                    FMA2(G1[2*j], wy, lo); FMA2(G1[2*j+1], wy, hi);
                }
            }
            #pragma unroll
            for (int j = 0; j < 8; j++) {
                float2 u = unpack2(G0[j]);
                bufB[w][r0*20 + 2*j]     = fmaxf(u.x, 0.f);
                bufB[w][r0*20 + 2*j + 1] = fmaxf(u.y, 0.f);
                float2 v = unpack2(G1[j]);
                bufB[w][r1*20 + 2*j]     = fmaxf(v.x, 0.f);
                bufB[w][r1*20 + 2*j + 1] = fmaxf(v.y, 0.f);
            }
        }
        __syncwarp();

        // S5: gamma = Wg2 * g + bg2  (packed)
        float gm0[16], gm1[16];
        {
            ull M0[8], M1[8];
            {
                ull b0 = pack2(bg2_0, bg2_0), b1 = pack2(bg2_1, bg2_1);
                #pragma unroll
                for (int j = 0; j < 8; j++) { M0[j] = b0; M1[j] = b1; }
            }
            #pragma unroll 4
            for (int c = 0; c < CH; c++) {
                float2 wv = *(const float2*)&g_WTg2[c*CH + r0];
                ull wx = pack2(wv.x, wv.x), wy = pack2(wv.y, wv.y);
                const float4* gr = (const float4*)&bufB[w][c*20];
                #pragma unroll
                for (int j = 0; j < 4; j++) {
                    float4 g4 = gr[j];
                    ull lo = pack2(g4.x, g4.y), hi = pack2(g4.z, g4.w);
                    FMA2(M0[2*j], wx, lo); FMA2(M0[2*j+1], wx, hi);
                    FMA2(M1[2*j], wy, lo); FMA2(M1[2*j+1], wy, hi);
                }
            }
            #pragma unroll
            for (int j = 0; j < 8; j++) {
                float2 u = unpack2(M0[j]); gm0[2*j] = u.x; gm0[2*j+1] = u.y;
                float2 v = unpack2(M1[j]); gm1[2*j] = v.x; gm1[2*j+1] = v.y;
            }
        }

        // S6: softmax over k, combine with alpha + delta, write output
        {
            float mx0 = gm0[0], mx1 = gm1[0];
            #pragma unroll
            for (int k = 1; k < 16; k++) { mx0 = fmaxf(mx0, gm0[k]); mx1 = fmaxf(mx1, gm1[k]); }
            float s0 = 0.f, s1 = 0.f;
            #pragma unroll
            for (int k = 0; k < 16; k++) {
                gm0[k] = __expf(gm0[k] - mx0); s0 += gm0[k];
                gm1[k] = __expf(gm1[k] - mx1); s1 += gm1[k];
            }
            float2 al = *(const float2*)&g_alphat[p*CH + r0];
            float acc0 = 0.f, acc1 = 0.f;
            #pragma unroll
            for (int k = 0; k < 16; k++) {
                acc0 = fmaf(gm0[k], al.x + d0[k], acc0);
                acc1 = fmaf(gm1[k], al.y + d1[k], acc1);
            }
            out[(size_t)b*CH*NP + (size_t)r0*NP + n] = acc0 / s0;
            out[(size_t)b*CH*NP + (size_t)r1*NP + n] = acc1 / s1;
        }
        __syncwarp();
    }
}

extern "C" void kernel_launch(void* const* d_in, const int* in_sizes, int n_in,
                              void* d_out, int out_size) {
    const float* features = (const float*)d_in[0];
    const float* coords   = (const float*)d_in[1];
    const float* W_phi    = (const float*)d_in[2];
    const float* b_phi    = (const float*)d_in[3];
    const float* W_psi    = (const float*)d_in[4];
    const float* b_psi    = (const float*)d_in[5];
    const float* W_alpha  = (const float*)d_in[6];
    const float* b_alpha  = (const float*)d_in[7];
    const float* W_g1     = (const float*)d_in[8];
    const float* b_g1     = (const float*)d_in[9];
    const float* W_g2     = (const float*)d_in[10];
    const float* b_g2     = (const float*)d_in[11];
    const float* W_d1     = (const float*)d_in[12];
    const float* b_d1     = (const float*)d_in[13];
    const float* W_d2     = (const float*)d_in[14];
    const float* b_d2     = (const float*)d_in[15];
    float* out = (float*)d_out;

    proj_kernel<<<512, 256>>>(features, coords, W_phi, b_phi, W_psi, b_psi,
                              W_alpha, b_alpha, W_g1, W_g2, W_d2);
    knn_kernel<<<256, 128>>>();
    agg_kernel<<<1024, 128>>>(W_d1, b_d1, b_d2, b_g1, b_g2, out);
}

// round 4
// speedup vs baseline: 1.3213x; 1.2220x over previous
#include <cuda_runtime.h>
#include <math.h>

#define BB 4
#define CH 64
#define NP 8192
#define KK 16
#define TOT (BB*NP)   /* 32768 points */
#define HALF 4096     /* candidates per knn block */

typedef unsigned long long ull;

// ---------------- packed f32x2 helpers (Blackwell sm_100+) ----------------
#define FMA2(acc, a, b) asm("fma.rn.f32x2 %0, %1, %2, %0;" : "+l"(acc) : "l"(a), "l"(b))
#define MUL2(d, a, b)   asm("mul.rn.f32x2 %0, %1, %2;"    : "=l"(d)   : "l"(a), "l"(b))
#define ADD2(d, a, b)   asm("add.rn.f32x2 %0, %1, %2;"    : "=l"(d)   : "l"(a), "l"(b))

__device__ __forceinline__ ull pack2(float x, float y) {
    ull r;
    asm("mov.b64 %0, {%1, %2};" : "=l"(r) : "f"(x), "f"(y));
    return r;
}
__device__ __forceinline__ float2 unpack2(ull v) {
    float2 r;
    asm("mov.b64 {%0, %1}, %2;" : "=f"(r.x), "=f"(r.y) : "l"(v));
    return r;
}

// ---------------- scratch (device globals; no allocation allowed) ----------------
__device__ float g_ft[TOT*CH];       // features, point-major  [p][c]
__device__ float g_phit[TOT*CH];     // phi,  point-major
__device__ float g_psit[TOT*CH];     // psi,  point-major
__device__ float g_alphat[TOT*CH];   // alpha, point-major
__device__ float g_sqn[TOT];         // |f|^2 per point
__device__ float g_coordst[TOT*3];   // coords, point-major [p][3]
__device__ int   g_knn[TOT*KK];      // knn indices (final)
__device__ float g_pval[32*TOT];     // partial top-16 values, layout [entry][point]
__device__ int   g_pidx[32*TOT];     // partial top-16 indices
__device__ float g_WTd2[CH*CH];      // W_d2 transposed [c][o]
__device__ float g_WTg1[CH*CH];      // W_g1 transposed [c][o]
__device__ float g_WTg2[CH*CH];      // W_g2 transposed [c][o]

// ======================= Kernel 1: projections + transposes =======================
__global__ void __launch_bounds__(256) proj_kernel(
    const float* __restrict__ feat, const float* __restrict__ coords,
    const float* __restrict__ Wphi, const float* __restrict__ bphi,
    const float* __restrict__ Wpsi, const float* __restrict__ bpsi,
    const float* __restrict__ Wal,  const float* __restrict__ bal,
    const float* __restrict__ Wg1,  const float* __restrict__ Wg2,
    const float* __restrict__ Wd2)
{
    __shared__ float WT[CH*CH];
    __shared__ float fbuf[8][8][CH];

    const int tid = threadIdx.x;
    const int w = tid >> 5, l = tid & 31;

    for (int p = blockIdx.x * 256 + tid; p < TOT; p += gridDim.x * 256) {
        int b = p >> 13, nn = p & (NP - 1);
        const float* cs = coords + b * 3 * NP + nn;
        g_coordst[p*3 + 0] = cs[0];
        g_coordst[p*3 + 1] = cs[NP];
        g_coordst[p*3 + 2] = cs[2*NP];
    }
    if (blockIdx.x == 0) {
        for (int i = tid; i < CH*CH; i += 256) {
            int o = i >> 6, c = i & 63;
            g_WTd2[c*CH + o] = Wd2[i];
            g_WTg1[c*CH + o] = Wg1[i];
            g_WTg2[c*CH + o] = Wg2[i];
        }
    }

    const int pbase = blockIdx.x * 64;

    #pragma unroll
    for (int i = 0; i < 8; i++) {
        int p = pbase + w * 8 + i;
        int b = p >> 13, nn = p & (NP - 1);
        float f0 = feat[(b*CH + 2*l    ) * NP + nn];
        float f1 = feat[(b*CH + 2*l + 1) * NP + nn];
        fbuf[w][i][2*l]     = f0;
        fbuf[w][i][2*l + 1] = f1;
        *(float2*)&g_ft[p*CH + 2*l] = make_float2(f0, f1);
        float sq = f0*f0 + f1*f1;
        #pragma unroll
        for (int off = 16; off; off >>= 1) sq += __shfl_xor_sync(0xffffffffu, sq, off);
        if (l == 0) g_sqn[p] = sq;
    }

    #pragma unroll 1
    for (int mat = 0; mat < 3; mat++) {
        const float* Wg = (mat == 0) ? Wphi : (mat == 1) ? Wpsi : Wal;
        const float* bg = (mat == 0) ? bphi : (mat == 1) ? bpsi : bal;
        float*       og = (mat == 0) ? g_phit : (mat == 1) ? g_psit : g_alphat;
        __syncthreads();
        for (int i = tid; i < CH*CH; i += 256) WT[(i & 63)*CH + (i >> 6)] = Wg[i];
        __syncthreads();
        float bb0 = bg[2*l], bb1 = bg[2*l + 1];
        #pragma unroll 1
        for (int i = 0; i < 8; i++) {
            int p = pbase + w * 8 + i;
            float a0 = bb0, a1 = bb1;
            const float4* fv4 = (const float4*)fbuf[w][i];
            #pragma unroll
            for (int c4 = 0; c4 < 16; c4++) {
                float4 fv = fv4[c4];
                float2 w0 = *(const float2*)&WT[(4*c4 + 0)*CH + 2*l];
                float2 w1 = *(const float2*)&WT[(4*c4 + 1)*CH + 2*l];
                float2 w2 = *(const float2*)&WT[(4*c4 + 2)*CH + 2*l];
                float2 w3 = *(const float2*)&WT[(4*c4 + 3)*CH + 2*l];
                a0 = fmaf(w0.x, fv.x, a0); a1 = fmaf(w0.y, fv.x, a1);
                a0 = fmaf(w1.x, fv.y, a0); a1 = fmaf(w1.y, fv.y, a1);
                a0 = fmaf(w2.x, fv.z, a0); a1 = fmaf(w2.y, fv.z, a1);
                a0 = fmaf(w3.x, fv.w, a0); a1 = fmaf(w3.y, fv.w, a1);
            }
            *(float2*)&og[p*CH + 2*l] = make_float2(a0, a1);
        }
    }
}

// ======================= Kernel 2: distance + partial top-16 ======================
// grid 256 = 128 query-chunks x 2 candidate-halves. 128 threads; each thread owns
// TWO queries (tid, tid+128) of its 256-query chunk, streaming 4096 candidates.
// Score: dot(2q, m) - |m|^2  (== reference neg_d + const). Top-16 lists in smem.
__global__ void __launch_bounds__(128) knn_kernel() {
    extern __shared__ float dyn[];
    float* sh   = dyn;                    // [128][68] candidate tile
    float* sqsh = dyn + 128*68;           // [128]
    float* tval = dyn + 128*68 + 128;     // [16][256] per-list top-16 values
    int*   tidx = (int*)(tval + 16*256);  // [16][256] per-list top-16 indices

    const int tid  = threadIdx.x;
    const int qc   = blockIdx.x >> 1;         // 0..127
    const int half = blockIdx.x & 1;
    const int b    = qc >> 5;                 // 32 chunks per batch
    const int q0   = ((qc & 31) << 8) + tid;  // within batch
    const int q1   = q0 + 128;
    const float* ft = g_ft + b * NP * CH;

    // load both query vectors, pre-scaled by 2, packed f32x2
    ull qa[32], qb[32];
    {
        const float4* pa = (const float4*)(ft + q0 * CH);
        const float4* pb = (const float4*)(ft + q1 * CH);
        #pragma unroll
        for (int j = 0; j < 16; j++) {
            float4 v = pa[j];
            qa[2*j]   = pack2(2.f*v.x, 2.f*v.y);
            qa[2*j+1] = pack2(2.f*v.z, 2.f*v.w);
            float4 u = pb[j];
            qb[2*j]   = pack2(2.f*u.x, 2.f*u.y);
            qb[2*j+1] = pack2(2.f*u.z, 2.f*u.w);
        }
    }

    const int lst0 = 2*tid, lst1 = 2*tid + 1;
    #pragma unroll
    for (int t = 0; t < 16; t++) {
        tval[t*256 + lst0] = -3.0e38f; tidx[t*256 + lst0] = 0;
        tval[t*256 + lst1] = -3.0e38f; tidx[t*256 + lst1] = 0;
    }
    float thr0 = -3.0e38f, thr1 = -3.0e38f;
    int   mp0 = 0, mp1 = 0;

    const int cbase = half * HALF;
    for (int tb = 0; tb < HALF; tb += 128) {
        __syncthreads();
        const float4* src = (const float4*)(ft + (cbase + tb) * CH);
        #pragma unroll
        for (int it = 0; it < 16; it++) {
            int i4 = tid + it * 128;
            int mi = i4 >> 4, c4 = i4 & 15;
            *(float4*)&sh[mi * 68 + 4 * c4] = src[i4];
        }
        sqsh[tid] = g_sqn[b * NP + cbase + tb + tid];
        __syncthreads();

        #pragma unroll 1
        for (int mi = 0; mi < 128; mi++) {
            const ulonglong2* row = (const ulonglong2*)&sh[mi * 68];  // broadcast LDS.128
            ull a0, a1, a2, a3, c0, c1, c2, c3;
            {
                ulonglong2 v = row[0];
                MUL2(a0, qa[0], v.x); MUL2(a1, qa[1], v.y);
                MUL2(c0, qb[0], v.x); MUL2(c1, qb[1], v.y);
                ulonglong2 u = row[1];
                MUL2(a2, qa[2], u.x); MUL2(a3, qa[3], u.y);
                MUL2(c2, qb[2], u.x); MUL2(c3, qb[3], u.y);
            }
            #pragma unroll
            for (int j = 2; j < 16; j += 2) {
                ulonglong2 v = row[j];
                FMA2(a0, qa[2*j],   v.x); FMA2(a1, qa[2*j+1], v.y);
                FMA2(c0, qb[2*j],   v.x); FMA2(c1, qb[2*j+1], v.y);
                ulonglong2 u = row[j+1];
                FMA2(a2, qa[2*j+2], u.x); FMA2(a3, qa[2*j+3], u.y);
                FMA2(c2, qb[2*j+2], u.x); FMA2(c3, qb[2*j+3], u.y);
            }
            float sq = sqsh[mi];
            ADD2(a0, a0, a2); ADD2(a1, a1, a3); ADD2(a0, a0, a1);
            ADD2(c0, c0, c2); ADD2(c1, c1, c3); ADD2(c0, c0, c1);
            float2 sa = unpack2(a0);
            float2 sb = unpack2(c0);
            float va = sa.x + sa.y - sq;
            float vb = sb.x + sb.y - sq;
            int m = cbase + tb + mi;
            if (va > thr0) {
                tval[mp0*256 + lst0] = va; tidx[mp0*256 + lst0] = m;
                float mn = tval[lst0]; int mp = 0;
                #pragma unroll
                for (int t = 1; t < 16; t++) {
                    float v = tval[t*256 + lst0];
                    if (v < mn) { mn = v; mp = t; }
                }
                thr0 = mn; mp0 = mp;
            }
            if (vb > thr1) {
                tval[mp1*256 + lst1] = vb; tidx[mp1*256 + lst1] = m;
                float mn = tval[lst1]; int mp = 0;
                #pragma unroll
                for (int t = 1; t < 16; t++) {
                    float v = tval[t*256 + lst1];
                    if (v < mn) { mn = v; mp = t; }
                }
                thr1 = mn; mp1 = mp;
            }
        }
    }

    // write partial lists: layout [entry e = half*16+t][point p]  (coalesced)
    const int p0 = b * NP + q0;
    const int p1 = b * NP + q1;
    #pragma unroll
    for (int t = 0; t < 16; t++) {
        int e = half * 16 + t;
        g_pval[e*TOT + p0] = tval[t*256 + lst0];
        g_pidx[e*TOT + p0] = tidx[t*256 + lst0];
        g_pval[e*TOT + p1] = tval[t*256 + lst1];
        g_pidx[e*TOT + p1] = tidx[t*256 + lst1];
    }
}

// ======================= Kernel 2b: merge two half top-16 lists ===================
// top-16-of-32 with exact (value desc, index asc) lexicographic ordering.
__global__ void __launch_bounds__(256) merge_kernel() {
    const int p = blockIdx.x * 256 + threadIdx.x;
    float bd[16]; int bi[16];
    #pragma unroll
    for (int t = 0; t < 16; t++) { bd[t] = -3.4e38f; bi[t] = 0x7fffffff; }
    float thrv = -3.4e38f; int thri = 0x7fffffff, mp = 0;

    #pragma unroll 1
    for (int e = 0; e < 32; e++) {
        float v = g_pval[e*TOT + p];
        int  ix = g_pidx[e*TOT + p];
        // insert if (v, ix) beats current worst (smaller v, or equal v & larger ix = worse)
        if (thrv < v || (thrv == v && thri > ix)) {
            bd[mp] = v; bi[mp] = ix;
            float mv = bd[0]; int mi2 = bi[0]; int mpos = 0;
            #pragma unroll
            for (int t = 1; t < 16; t++) {
                if (bd[t] < mv || (bd[t] == mv && bi[t] > mi2)) { mv = bd[t]; mi2 = bi[t]; mpos = t; }
            }
            thrv = mv; thri = mi2; mp = mpos;
        }
    }
    int* dst = g_knn + p * KK;
    #pragma unroll
    for (int t = 0; t < 16; t++) dst[t] = bi[t];
}

// ======================= Kernel 3: per-neighbor MLP + softmax (f32x2 GEMMs) =======
__global__ void __launch_bounds__(128) agg_kernel(
    const float* __restrict__ Wd1, const float* __restrict__ bd1,
    const float* __restrict__ bd2, const float* __restrict__ bg1,
    const float* __restrict__ bg2, float* __restrict__ out)
{
    __shared__ float bufA[4][CH * 20];
    __shared__ float bufB[4][CH * 20];
    __shared__ float cds[4][48];
    __shared__ int   idxs[4][16];

    const int w = threadIdx.x >> 5, l = threadIdx.x & 31;
    const int r0 = 2 * l, r1 = 2 * l + 1;

    const float w00 = Wd1[r0*3+0], w01 = Wd1[r0*3+1], w02 = Wd1[r0*3+2];
    const float w10 = Wd1[r1*3+0], w11 = Wd1[r1*3+1], w12 = Wd1[r1*3+2];
    const float bd1_0 = bd1[r0], bd1_1 = bd1[r1];
    const float bd2_0 = bd2[r0], bd2_1 = bd2[r1];
    const float bg1_0 = bg1[r0], bg1_1 = bg1[r1];
    const float bg2_0 = bg2[r0], bg2_1 = bg2[r1];

    #pragma unroll 1
    for (int i = 0; i < 8; i++) {
        const int p = (blockIdx.x * 4 + w) * 8 + i;
        const int b = p >> 13, n = p & (NP - 1);

        if (l < 16) {
            int m = g_knn[p * KK + l];
            idxs[w][l] = m;
            const float* cn = g_coordst + p * 3;
            const float* cm = g_coordst + (b * NP + m) * 3;
            cds[w][l]      = cn[0] - cm[0];
            cds[w][16 + l] = cn[1] - cm[1];
            cds[w][32 + l] = cn[2] - cm[2];
        }
        __syncwarp();

        #pragma unroll
        for (int k = 0; k < 16; k++) {
            float c0 = cds[w][k], c1 = cds[w][16 + k], c2 = cds[w][32 + k];
            float h0 = fmaxf(fmaf(w02, c2, fmaf(w01, c1, fmaf(w00, c0, bd1_0))), 0.f);
            float h1 = fmaxf(fmaf(w12, c2, fmaf(w11, c1, fmaf(w10, c0, bd1_1))), 0.f);
            bufA[w][r0*20 + k] = h0;
            bufA[w][r1*20 + k] = h1;
        }
        __syncwarp();

        ull D0[8], D1[8];
        {
            ull b0 = pack2(bd2_0, bd2_0), b1 = pack2(bd2_1, bd2_1);
            #pragma unroll
            for (int j = 0; j < 8; j++) { D0[j] = b0; D1[j] = b1; }
        }
        #pragma unroll 4
        for (int c = 0; c < CH; c++) {
            float2 wv = *(const float2*)&g_WTd2[c*CH + r0];
            ull wx = pack2(wv.x, wv.x), wy = pack2(wv.y, wv.y);
            const ulonglong2* hr = (const ulonglong2*)&bufA[w][c*20];
            #pragma unroll
            for (int j = 0; j < 4; j++) {
                ulonglong2 h2 = hr[j];
                FMA2(D0[2*j], wx, h2.x); FMA2(D0[2*j+1], wx, h2.y);
                FMA2(D1[2*j], wy, h2.x); FMA2(D1[2*j+1], wy, h2.y);
            }
        }
        float d0[16], d1[16];
        #pragma unroll
        for (int j = 0; j < 8; j++) {
            float2 u = unpack2(D0[j]); d0[2*j] = u.x; d0[2*j+1] = u.y;
            float2 v = unpack2(D1[j]); d1[2*j] = v.x; d1[2*j+1] = v.y;
        }
        __syncwarp();

        {
            float2 ph = *(const float2*)&g_phit[p*CH + r0];
            #pragma unroll
            for (int k = 0; k < 16; k++) {
                int m = idxs[w][k];
                float2 ps = *(const float2*)&g_psit[(size_t)(b*NP + m)*CH + r0];
                bufA[w][r0*20 + k] = ph.x - ps.x + d0[k];
                bufA[w][r1*20 + k] = ph.y - ps.y + d1[k];
            }
        }
        __syncwarp();

        {
            ull G0[8], G1[8];
            {
                ull b0 = pack2(bg1_0, bg1_0), b1 = pack2(bg1_1, bg1_1);
                #pragma unroll
                for (int j = 0; j < 8; j++) { G0[j] = b0; G1[j] = b1; }
            }
            #pragma unroll 4
            for (int c = 0; c < CH; c++) {
                float2 wv = *(const float2*)&g_WTg1[c*CH + r0];
                ull wx = pack2(wv.x, wv.x), wy = pack2(wv.y, wv.y);
                const ulonglong2* xr = (const ulonglong2*)&bufA[w][c*20];
                #pragma unroll
                for (int j = 0; j < 4; j++) {
                    ulonglong2 x2 = xr[j];
                    FMA2(G0[2*j], wx, x2.x); FMA2(G0[2*j+1], wx, x2.y);
                    FMA2(G1[2*j], wy, x2.x); FMA2(G1[2*j+1], wy, x2.y);
                }
            }
            #pragma unroll
            for (int j = 0; j < 8; j++) {
                float2 u = unpack2(G0[j]);
                bufB[w][r0*20 + 2*j]     = fmaxf(u.x, 0.f);
                bufB[w][r0*20 + 2*j + 1] = fmaxf(u.y, 0.f);
                float2 v = unpack2(G1[j]);
                bufB[w][r1*20 + 2*j]     = fmaxf(v.x, 0.f);
                bufB[w][r1*20 + 2*j + 1] = fmaxf(v.y, 0.f);
            }
        }
        __syncwarp();

        float gm0[16], gm1[16];
        {
            ull M0[8], M1[8];
            {
                ull b0 = pack2(bg2_0, bg2_0), b1 = pack2(bg2_1, bg2_1);
                #pragma unroll
                for (int j = 0; j < 8; j++) { M0[j] = b0; M1[j] = b1; }
            }
            #pragma unroll 4
            for (int c = 0; c < CH; c++) {
                float2 wv = *(const float2*)&g_WTg2[c*CH + r0];
                ull wx = pack2(wv.x, wv.x), wy = pack2(wv.y, wv.y);
                const ulonglong2* gr = (const ulonglong2*)&bufB[w][c*20];
                #pragma unroll
                for (int j = 0; j < 4; j++) {
                    ulonglong2 g2 = gr[j];
                    FMA2(M0[2*j], wx, g2.x); FMA2(M0[2*j+1], wx, g2.y);
                    FMA2(M1[2*j], wy, g2.x); FMA2(M1[2*j+1], wy, g2.y);
                }
            }
            #pragma unroll
            for (int j = 0; j < 8; j++) {
                float2 u = unpack2(M0[j]); gm0[2*j] = u.x; gm0[2*j+1] = u.y;
                float2 v = unpack2(M1[j]); gm1[2*j] = v.x; gm1[2*j+1] = v.y;
            }
        }

        {
            float mx0 = gm0[0], mx1 = gm1[0];
            #pragma unroll
            for (int k = 1; k < 16; k++) { mx0 = fmaxf(mx0, gm0[k]); mx1 = fmaxf(mx1, gm1[k]); }
            float s0 = 0.f, s1 = 0.f;
            #pragma unroll
            for (int k = 0; k < 16; k++) {
                gm0[k] = __expf(gm0[k] - mx0); s0 += gm0[k];
                gm1[k] = __expf(gm1[k] - mx1); s1 += gm1[k];
            }
            float2 al = *(const float2*)&g_alphat[p*CH + r0];
            float acc0 = 0.f, acc1 = 0.f;
            #pragma unroll
            for (int k = 0; k < 16; k++) {
                acc0 = fmaf(gm0[k], al.x + d0[k], acc0);
                acc1 = fmaf(gm1[k], al.y + d1[k], acc1);
            }
            out[(size_t)b*CH*NP + (size_t)r0*NP + n] = acc0 / s0;
            out[(size_t)b*CH*NP + (size_t)r1*NP + n] = acc1 / s1;
        }
        __syncwarp();
    }
}

extern "C" void kernel_launch(void* const* d_in, const int* in_sizes, int n_in,
                              void* d_out, int out_size) {
    const float* features = (const float*)d_in[0];
    const float* coords   = (const float*)d_in[1];
    const float* W_phi    = (const float*)d_in[2];
    const float* b_phi    = (const float*)d_in[3];
    const float* W_psi    = (const float*)d_in[4];
    const float* b_psi    = (const float*)d_in[5];
    const float* W_alpha  = (const float*)d_in[6];
    const float* b_alpha  = (const float*)d_in[7];
    const float* W_g1     = (const float*)d_in[8];
    const float* b_g1     = (const float*)d_in[9];
    const float* W_g2     = (const float*)d_in[10];
    const float* b_g2     = (const float*)d_in[11];
    const float* W_d1     = (const float*)d_in[12];
    const float* b_d1     = (const float*)d_in[13];
    const float* W_d2     = (const float*)d_in[14];
    const float* b_d2     = (const float*)d_in[15];
    float* out = (float*)d_out;

    // knn smem: tile 128*68 + sqn 128 + topk vals 16*256 + topk idx 16*256
    const int knn_smem = (128*68 + 128 + 16*256) * 4 + 16*256*4;  // 68096 B
    static int attr_done = 0;
    if (!attr_done) {
        cudaFuncSetAttribute(knn_kernel, cudaFuncAttributeMaxDynamicSharedMemorySize, knn_smem);
        attr_done = 1;
    }

    proj_kernel<<<512, 256>>>(features, coords, W_phi, b_phi, W_psi, b_psi,
                              W_alpha, b_alpha, W_g1, W_g2, W_d2);
    knn_kernel<<<256, 128, knn_smem>>>();
    merge_kernel<<<128, 256>>>();
    agg_kernel<<<1024, 128>>>(W_d1, b_d1, b_d2, b_g1, b_g2, out);
}